// round 2
// baseline (speedup 1.0000x reference)
#include <cuda_runtime.h>
#include <cstdint>

// Problem constants
#define NWIN      2048            // 32 batches * 64 windows
#define HEADS     8
#define WS2       64
#define HEAD_DIM  32
#define DIMC      256
#define QKV_PART  (NWIN * HEADS * WS2 * HEAD_DIM)   // 33,554,432 floats per q/k/v
#define SCALE_F   0.17677669529663687f              // 32^-0.5

// Scratch (static device globals — allocation-free per harness rules)
__device__ float g_qkv[3ULL * QKV_PART];            // [part][g][h][t][d]
__device__ float g_o[(size_t)NWIN * WS2 * DIMC];    // [g][t][c] merged-head attn output

// ---------------------------------------------------------------------------
// GEMM over windows: C[64 x Ntile] = A[64 x 256] * W^T + bias
// MODE 0: A = x gathered via roll+window map; C -> g_qkv (q/k/v split layout)
// MODE 1: A = g_o (contiguous); C -> d_out scattered via inverse roll
// Tile: BM=64 (tokens), BN=128, BK=16. 256 threads, 4x8 micro-tile per thread.
// ---------------------------------------------------------------------------
template <int MODE>
__global__ __launch_bounds__(256)
void gemm_win_kernel(const float* __restrict__ A,
                     const float* __restrict__ W,
                     const float* __restrict__ bias,
                     float* __restrict__ C)
{
    __shared__ float As[16][64];
    __shared__ float Bs[16][128];
    __shared__ int   rowOff[64];

    const int tid = threadIdx.x;
    const int g   = blockIdx.y;     // global window id
    const int nt  = blockIdx.x;     // N tile (128 cols each)

    const int b  = g >> 6;
    const int w  = g & 63;
    const int wy = w >> 3, wx = w & 7;

    if (tid < 64) {
        const int ty = tid >> 3, tx = tid & 7;
        const int i_ = (wy * 8 + ty + 4) & 63;   // roll(-4) gather == roll(+4) scatter
        const int j_ = (wx * 8 + tx + 4) & 63;
        rowOff[tid] = (b * 4096 + i_ * 64 + j_) * DIMC;
    }
    __syncthreads();

    const int cy = tid >> 4;         // 0..15
    const int cx = tid & 15;         // 0..15
    const int m0 = cy * 4;
    const int n0 = cx * 8;

    float acc[4][8];
#pragma unroll
    for (int i = 0; i < 4; i++)
#pragma unroll
        for (int j = 0; j < 8; j++) acc[i][j] = 0.f;

    // cooperative load indices
    const int at = tid >> 2;             // token row for A
    const int ak = (tid & 3) << 2;       // k offset (float4)
    const int bn = tid >> 1;             // n row for B
    const int bk = (tid & 1) << 3;       // k offset (2x float4)

    const float* arow = (MODE == 0)
        ? (A + rowOff[at] )
        : ((const float*)g_o + ((size_t)g * 64 + at) * DIMC);
    const float* brow = W + ((size_t)(nt * 128 + bn)) * DIMC;

    for (int kc = 0; kc < 256; kc += 16) {
        const float4 av  = *(const float4*)(arow + kc + ak);
        const float4 bv0 = *(const float4*)(brow + kc + bk);
        const float4 bv1 = *(const float4*)(brow + kc + bk + 4);
        As[ak + 0][at] = av.x;  As[ak + 1][at] = av.y;
        As[ak + 2][at] = av.z;  As[ak + 3][at] = av.w;
        Bs[bk + 0][bn] = bv0.x; Bs[bk + 1][bn] = bv0.y;
        Bs[bk + 2][bn] = bv0.z; Bs[bk + 3][bn] = bv0.w;
        Bs[bk + 4][bn] = bv1.x; Bs[bk + 5][bn] = bv1.y;
        Bs[bk + 6][bn] = bv1.z; Bs[bk + 7][bn] = bv1.w;
        __syncthreads();
#pragma unroll
        for (int kk = 0; kk < 16; kk++) {
            const float4 a = *(const float4*)&As[kk][m0];
            const float4 p = *(const float4*)&Bs[kk][n0];
            const float4 q = *(const float4*)&Bs[kk][n0 + 4];
            const float av_[4] = {a.x, a.y, a.z, a.w};
            const float bv_[8] = {p.x, p.y, p.z, p.w, q.x, q.y, q.z, q.w};
#pragma unroll
            for (int i = 0; i < 4; i++)
#pragma unroll
                for (int j = 0; j < 8; j++)
                    acc[i][j] += av_[i] * bv_[j];
        }
        __syncthreads();
    }

    // epilogue
#pragma unroll
    for (int i = 0; i < 4; i++) {
        const int t = m0 + i;
        if (MODE == 0) {
            // nn -> (part, head, d); within 8 cols head/part constant (n0 % 32 in {0,8,16,24})
#pragma unroll
            for (int j = 0; j < 8; j++) {
                const int nn   = nt * 128 + n0 + j;
                const float v  = acc[i][j] + bias[nn];
                const int part = nn >> 8;
                const int rem  = nn & 255;
                const int h    = rem >> 5;
                const int d    = rem & 31;
                g_qkv[(size_t)part * QKV_PART +
                      (((size_t)(g * 8 + h)) * 64 + t) * 32 + d] = v;
            }
        } else {
            const int nn0 = nt * 128 + n0;
            float4 o0, o1;
            o0.x = acc[i][0] + bias[nn0 + 0]; o0.y = acc[i][1] + bias[nn0 + 1];
            o0.z = acc[i][2] + bias[nn0 + 2]; o0.w = acc[i][3] + bias[nn0 + 3];
            o1.x = acc[i][4] + bias[nn0 + 4]; o1.y = acc[i][5] + bias[nn0 + 5];
            o1.z = acc[i][6] + bias[nn0 + 6]; o1.w = acc[i][7] + bias[nn0 + 7];
            float* dst = C + rowOff[t] + nn0;
            *(float4*)(dst)     = o0;
            *(float4*)(dst + 4) = o1;
        }
    }
}

// ---------------------------------------------------------------------------
// Attention core: one block per (window g, head h). 64 threads; thread t owns
// query row t. K/V staged in smem (broadcast reads), bias and shift-mask
// computed analytically, per-thread softmax (no cross-thread reduction).
// ---------------------------------------------------------------------------
__global__ __launch_bounds__(64)
void attn_kernel(const float* __restrict__ pos_enc)
{
    __shared__ float Ks[WS2 * HEAD_DIM];
    __shared__ float Vs[WS2 * HEAD_DIM];
    __shared__ float pe[225];

    const int gh = blockIdx.x;
    const int g  = gh >> 3;
    const int h  = gh & 7;
    const int t  = threadIdx.x;

    const float* Qb = g_qkv + (size_t)gh * 2048;
    const float* Kb = g_qkv + (size_t)QKV_PART + (size_t)gh * 2048;
    const float* Vb = g_qkv + 2ULL * QKV_PART + (size_t)gh * 2048;

    for (int i = t; i < 512; i += 64) {
        ((float4*)Ks)[i] = ((const float4*)Kb)[i];
        ((float4*)Vs)[i] = ((const float4*)Vb)[i];
    }
    for (int i = t; i < 225; i += 64) pe[i] = pos_enc[h * 225 + i];

    float q[32];
#pragma unroll
    for (int i = 0; i < 8; i++) {
        const float4 v = ((const float4*)(Qb + (size_t)t * 32))[i];
        q[i * 4 + 0] = v.x; q[i * 4 + 1] = v.y;
        q[i * 4 + 2] = v.z; q[i * 4 + 3] = v.w;
    }
    __syncthreads();

    const int w  = g & 63;
    const int wy = w >> 3, wx = w & 7;
    const int ty = t >> 3, tx = t & 7;
    const int rq = ((wy == 7) ? (ty < 4 ? 1 : 2) : 0) * 3 +
                   ((wx == 7) ? (tx < 4 ? 1 : 2) : 0);

    float s[64];
#pragma unroll
    for (int k = 0; k < 64; k++) {
        float acc = 0.f;
#pragma unroll
        for (int d4 = 0; d4 < 8; d4++) {
            const float4 kv = ((const float4*)(Ks + k * 32))[d4];
            acc += q[d4 * 4 + 0] * kv.x + q[d4 * 4 + 1] * kv.y +
                   q[d4 * 4 + 2] * kv.z + q[d4 * 4 + 3] * kv.w;
        }
        const int ky = k >> 3, kx = k & 7;
        const int rk = ((wy == 7) ? (ky < 4 ? 1 : 2) : 0) * 3 +
                       ((wx == 7) ? (kx < 4 ? 1 : 2) : 0);
        const float val = acc * SCALE_F + pe[(ty - ky + 7) * 15 + (tx - kx + 7)];
        s[k] = (rk != rq) ? -1e30f : val;
    }

    float m = -1e30f;
#pragma unroll
    for (int k = 0; k < 64; k++) m = fmaxf(m, s[k]);
    float sum = 0.f;
#pragma unroll
    for (int k = 0; k < 64; k++) { s[k] = __expf(s[k] - m); sum += s[k]; }
    const float inv = 1.f / sum;

    float o[32];
#pragma unroll
    for (int d = 0; d < 32; d++) o[d] = 0.f;
#pragma unroll
    for (int k = 0; k < 64; k++) {
        const float p = s[k];
#pragma unroll
        for (int d4 = 0; d4 < 8; d4++) {
            const float4 vv = ((const float4*)(Vs + k * 32))[d4];
            o[d4 * 4 + 0] += p * vv.x; o[d4 * 4 + 1] += p * vv.y;
            o[d4 * 4 + 2] += p * vv.z; o[d4 * 4 + 3] += p * vv.w;
        }
    }

    float* Ob = g_o + (((size_t)g * 64 + t) * DIMC) + h * 32;
#pragma unroll
    for (int d4 = 0; d4 < 8; d4++) {
        float4 ov;
        ov.x = o[d4 * 4 + 0] * inv; ov.y = o[d4 * 4 + 1] * inv;
        ov.z = o[d4 * 4 + 2] * inv; ov.w = o[d4 * 4 + 3] * inv;
        *(float4*)(Ob + d4 * 4) = ov;
    }
}

// ---------------------------------------------------------------------------
extern "C" void kernel_launch(void* const* d_in, const int* in_sizes, int n_in,
                              void* d_out, int out_size)
{
    const float* x       = (const float*)d_in[0];
    const float* w_qkv   = (const float*)d_in[1];
    const float* b_qkv   = (const float*)d_in[2];
    const float* w_out   = (const float*)d_in[3];
    const float* b_out   = (const float*)d_in[4];
    const float* pos_enc = (const float*)d_in[5];
    float* out = (float*)d_out;

    // 1) roll + window gather + QKV projection (N = 768 -> 6 tiles of 128)
    gemm_win_kernel<0><<<dim3(6, NWIN), 256>>>(x, w_qkv, b_qkv, nullptr);
    // 2) windowed attention per (window, head)
    attn_kernel<<<NWIN * HEADS, 64>>>(pos_enc);
    // 3) output projection + inverse roll scatter (N = 256 -> 2 tiles)
    gemm_win_kernel<1><<<dim3(2, NWIN), 256>>>(nullptr, w_out, b_out, out);
}

// round 5
// speedup vs baseline: 1.7789x; 1.7789x over previous
#include <cuda_runtime.h>
#include <cuda_bf16.h>
#include <cstdint>

// ---------------------------------------------------------------------------
// Problem constants
// ---------------------------------------------------------------------------
#define NWIN      2048
#define HEADS     8
#define WS2       64
#define HEAD_DIM  32
#define DIMC      256
#define QKV_PART  (NWIN * HEADS * WS2 * HEAD_DIM)   // 33,554,432
#define SCALE_F   0.17677669529663687f

// Scratch (static device globals — allocation-free per harness rules)
__device__ float          g_qkv[3ULL * QKV_PART];   // [part][g][h][t][d] fp32
__device__ unsigned int   g_xhi32[16777216];        // bf16 pairs of x (later: attn out), [row][k/2]
__device__ unsigned int   g_xlo32[16777216];
__device__ unsigned short g_wqhi[196608];           // w_qkv row-major bf16 hi/lo [768][256]
__device__ unsigned short g_wqlo[196608];
__device__ unsigned short g_wohi[65536];            // w_out  row-major bf16 hi/lo [256][256]
__device__ unsigned short g_wolo[65536];

// ---------------------------------------------------------------------------
// Helpers (plain-target PTX only: ldmatrix / mma.sync / cp.async)
// ---------------------------------------------------------------------------
__device__ __forceinline__ uint32_t smem_u32(const void* p) {
    uint32_t a;
    asm("{ .reg .u64 t; cvta.to.shared.u64 t, %1; cvt.u32.u64 %0, t; }" : "=r"(a) : "l"(p));
    return a;
}
__device__ __forceinline__ void cp16(uint32_t dst, const void* src) {
    asm volatile("cp.async.cg.shared.global [%0], [%1], 16;" :: "r"(dst), "l"(src));
}
#define CP_COMMIT()  asm volatile("cp.async.commit_group;")
#define CP_WAIT(n)   asm volatile("cp.async.wait_group %0;" :: "n"(n))

#define LDM4(r, addr) \
    asm volatile("ldmatrix.sync.aligned.m8n8.x4.shared.b16 {%0,%1,%2,%3}, [%4];" \
        : "=r"((r)[0]), "=r"((r)[1]), "=r"((r)[2]), "=r"((r)[3]) : "r"(addr))

#define MMA16816(c, a, b0, b1) \
    asm volatile("mma.sync.aligned.m16n8k16.row.col.f32.bf16.bf16.f32 " \
        "{%0,%1,%2,%3},{%4,%5,%6,%7},{%8,%9},{%0,%1,%2,%3};" \
        : "+f"((c)[0]), "+f"((c)[1]), "+f"((c)[2]), "+f"((c)[3]) \
        : "r"((a)[0]), "r"((a)[1]), "r"((a)[2]), "r"((a)[3]), "r"(b0), "r"(b1))

__device__ __forceinline__ unsigned short bf_hi(float f) {
    return __bfloat16_as_ushort(__float2bfloat16_rn(f));
}

// ---------------------------------------------------------------------------
// prep_x: split fp32 -> bf16 hi/lo packed-pair arrays (4 floats/thread)
// ---------------------------------------------------------------------------
__global__ __launch_bounds__(256) void prep_x_kernel(const float4* __restrict__ x4)
{
    const int gid = blockIdx.x * 256 + threadIdx.x;   // 8,388,608
    const float4 v = x4[gid];
    __nv_bfloat16 h0 = __float2bfloat16_rn(v.x), h1 = __float2bfloat16_rn(v.y);
    __nv_bfloat16 h2 = __float2bfloat16_rn(v.z), h3 = __float2bfloat16_rn(v.w);
    uint2 H, L;
    H.x = (uint32_t)__bfloat16_as_ushort(h0) | ((uint32_t)__bfloat16_as_ushort(h1) << 16);
    H.y = (uint32_t)__bfloat16_as_ushort(h2) | ((uint32_t)__bfloat16_as_ushort(h3) << 16);
    L.x = (uint32_t)bf_hi(v.x - __bfloat162float(h0)) | ((uint32_t)bf_hi(v.y - __bfloat162float(h1)) << 16);
    L.y = (uint32_t)bf_hi(v.z - __bfloat162float(h2)) | ((uint32_t)bf_hi(v.w - __bfloat162float(h3)) << 16);
    ((uint2*)g_xhi32)[gid] = H;
    ((uint2*)g_xlo32)[gid] = L;
}

// ---------------------------------------------------------------------------
// prep_w: weights -> row-major bf16 hi/lo
// ---------------------------------------------------------------------------
__global__ __launch_bounds__(256) void prep_w_kernel(const float* __restrict__ wq,
                                                     const float* __restrict__ wo)
{
    const int idx = blockIdx.x * 256 + threadIdx.x;   // 262,144
    if (idx < 196608) {
        const float v = wq[idx];
        __nv_bfloat16 h = __float2bfloat16_rn(v);
        g_wqhi[idx] = __bfloat16_as_ushort(h);
        g_wqlo[idx] = bf_hi(v - __bfloat162float(h));
    } else {
        const int i2 = idx - 196608;
        const float v = wo[i2];
        __nv_bfloat16 h = __float2bfloat16_rn(v);
        g_wohi[i2] = __bfloat16_as_ushort(h);
        g_wolo[i2] = bf_hi(v - __bfloat162float(h));
    }
}

// ---------------------------------------------------------------------------
// HMMA GEMM: block = [128 rows x 128 cols], K=256 in 8 chunks of 32,
// cp.async double-buffered. 8 warps, each 32 rows x 64 cols.
// 3-term bf16 split: Ahi*Bhi + Ahi*Blo + Alo*Bhi (fp32 accum).
// MODE 0: A = x (roll+window gather rows), C -> g_qkv split layout.
// MODE 1: A = attn out (contiguous rows),  C -> d_out (inverse-roll scatter).
// smem tile: 128 rows * 80B stride (32 bf16 data + 16B pad): ldmatrix conflict-free.
// ---------------------------------------------------------------------------
#define TILE_B    10240               // 128*80
#define BUF_B     (4 * TILE_B)        // Ahi, Alo, Bhi, Blo
#define SMEM_DYN  (2 * BUF_B)         // 81920

template <int MODE>
__global__ __launch_bounds__(256)
void gemm_mma_kernel(const float* __restrict__ bias, float* __restrict__ out)
{
    extern __shared__ char smem[];
    __shared__ int   rowoff[128];
    __shared__ float bias_s[128];

    const uint32_t sb  = smem_u32(smem);
    const int tid  = threadIdx.x;
    const int wid  = tid >> 5;
    const int lane = tid & 31;
    const int nt = blockIdx.x, mb = blockIdx.y;

    // per-block row map (roll + window gather/scatter) and bias slice
    if (tid < 128) {
        const int r = tid;
        const int g = mb * 2 + (r >> 6);
        const int b = g >> 6, w = g & 63;
        const int wy = w >> 3, wx = w & 7, ty = (r >> 3) & 7, tx = r & 7;
        const int i_ = (wy * 8 + ty + 4) & 63;
        const int j_ = (wx * 8 + tx + 4) & 63;
        const int srcRow = b * 4096 + i_ * 64 + j_;
        rowoff[r] = (MODE == 0) ? srcRow * 128 : srcRow * 256;  // uint-pairs | floats
        bias_s[r] = bias[nt * 128 + r];
    }
    __syncthreads();

    const unsigned short* wh = (MODE == 0) ? g_wqhi : g_wohi;
    const unsigned short* wl = (MODE == 0) ? g_wqlo : g_wolo;

    // loader: thread -> (row = tid>>1, two 16B quads)
    const int lrow = tid >> 1;
    const int q0   = (tid & 1) * 2;
    const int aRowBase = (MODE == 0) ? rowoff[lrow] : (mb * 128 + lrow) * 128;  // uint idx
    const int bRowBase = (nt * 128 + lrow) * 256;                                // ushort idx

    float acc[2][8][4];
#pragma unroll
    for (int i = 0; i < 2; i++)
#pragma unroll
        for (int j = 0; j < 8; j++)
#pragma unroll
            for (int k = 0; k < 4; k++) acc[i][j][k] = 0.f;

    // ldmatrix lane offsets (stride 80B)
    const int a_off = ((lane & 7) + ((lane >> 3) & 1) * 8) * 80 + (lane >> 4) * 16;
    const int b_off = ((lane & 7) + ((lane >> 3) >> 1) * 8) * 80 + ((lane >> 3) & 1) * 16;
    const int wr = wid & 3;      // warp row: 32 rows
    const int wc = wid >> 2;     // warp col: 64 cols

#define LOAD_CHUNK(kc, buf) do { \
    const uint32_t base = sb + (buf) * BUF_B + lrow * 80; \
    _Pragma("unroll") \
    for (int j = 0; j < 2; j++) { \
        const int q = q0 + j; \
        const uint32_t d = base + q * 16; \
        cp16(d,              g_xhi32 + aRowBase + (kc) * 16 + q * 4); \
        cp16(d + TILE_B,     g_xlo32 + aRowBase + (kc) * 16 + q * 4); \
        cp16(d + 2 * TILE_B, wh + bRowBase + (kc) * 32 + q * 8); \
        cp16(d + 3 * TILE_B, wl + bRowBase + (kc) * 32 + q * 8); \
    } \
} while (0)

    LOAD_CHUNK(0, 0);
    CP_COMMIT();

    for (int kc = 0; kc < 8; kc++) {
        if (kc < 7) {
            LOAD_CHUNK(kc + 1, (kc + 1) & 1);
            CP_COMMIT();
            CP_WAIT(1);
        } else {
            CP_WAIT(0);
        }
        __syncthreads();

        const uint32_t Ab = sb + (kc & 1) * BUF_B;
        const uint32_t Bb = Ab + 2 * TILE_B;
#pragma unroll
        for (int ks = 0; ks < 2; ks++) {
            uint32_t ah[2][4], al[2][4];
#pragma unroll
            for (int mt = 0; mt < 2; mt++) {
                const uint32_t ad = Ab + (wr * 32 + mt * 16) * 80 + ks * 32 + a_off;
                LDM4(ah[mt], ad);
                LDM4(al[mt], ad + TILE_B);
            }
#pragma unroll
            for (int np = 0; np < 4; np++) {
                uint32_t bh[4], bl[4];
                const uint32_t bd = Bb + (wc * 64 + np * 16) * 80 + ks * 32 + b_off;
                LDM4(bh, bd);
                LDM4(bl, bd + TILE_B);
#pragma unroll
                for (int mt = 0; mt < 2; mt++) {
#pragma unroll
                    for (int sub = 0; sub < 2; sub++) {
                        float* c = acc[mt][np * 2 + sub];
                        MMA16816(c, ah[mt], bh[2 * sub], bh[2 * sub + 1]);
                        MMA16816(c, ah[mt], bl[2 * sub], bl[2 * sub + 1]);
                        MMA16816(c, al[mt], bh[2 * sub], bh[2 * sub + 1]);
                    }
                }
            }
        }
        __syncthreads();
    }

    // epilogue: fragment (d0,d1)->(row m, col c,c+1); (d2,d3)->(row m+8)
#pragma unroll
    for (int mt = 0; mt < 2; mt++) {
        const int R0 = wr * 32 + mt * 16 + (lane >> 2);
#pragma unroll
        for (int nti = 0; nti < 8; nti++) {
            const int cb = wc * 64 + nti * 8 + (lane & 3) * 2;   // col in block
            const float bz0 = bias_s[cb], bz1 = bias_s[cb + 1];
            const float* c = acc[mt][nti];
#pragma unroll
            for (int half = 0; half < 2; half++) {
                const int R = R0 + half * 8;
                float2 v;
                v.x = c[half * 2 + 0] + bz0;
                v.y = c[half * 2 + 1] + bz1;
                if (MODE == 0) {
                    const int nn   = nt * 128 + cb;
                    const int part = nn >> 8;
                    const int h    = (nn & 255) >> 5;
                    const int d    = nn & 31;
                    const int g    = mb * 2 + (R >> 6);
                    const int t    = R & 63;
                    *(float2*)(g_qkv + (size_t)part * QKV_PART +
                               (((size_t)(g * 8 + h)) * 64 + t) * 32 + d) = v;
                } else {
                    *(float2*)(out + rowoff[R] + nt * 128 + cb) = v;
                }
            }
        }
    }
}

// ---------------------------------------------------------------------------
// Attention core (fp32 SIMT); epilogue writes bf16 hi/lo pairs into
// g_xhi32/g_xlo32 (row = g*64+t, 128 uints) for the out-projection GEMM.
// ---------------------------------------------------------------------------
__global__ __launch_bounds__(64)
void attn_kernel(const float* __restrict__ pos_enc)
{
    __shared__ float Ks[WS2 * HEAD_DIM];
    __shared__ float Vs[WS2 * HEAD_DIM];
    __shared__ float pe[225];

    const int gh = blockIdx.x;
    const int g  = gh >> 3;
    const int h  = gh & 7;
    const int t  = threadIdx.x;

    const float* Qb = g_qkv + (size_t)gh * 2048;
    const float* Kb = g_qkv + (size_t)QKV_PART + (size_t)gh * 2048;
    const float* Vb = g_qkv + 2ULL * QKV_PART + (size_t)gh * 2048;

    for (int i = t; i < 512; i += 64) {
        ((float4*)Ks)[i] = ((const float4*)Kb)[i];
        ((float4*)Vs)[i] = ((const float4*)Vb)[i];
    }
    for (int i = t; i < 225; i += 64) pe[i] = pos_enc[h * 225 + i];

    float q[32];
#pragma unroll
    for (int i = 0; i < 8; i++) {
        const float4 v = ((const float4*)(Qb + (size_t)t * 32))[i];
        q[i * 4 + 0] = v.x; q[i * 4 + 1] = v.y;
        q[i * 4 + 2] = v.z; q[i * 4 + 3] = v.w;
    }
    __syncthreads();

    const int w  = g & 63;
    const int wy = w >> 3, wx = w & 7;
    const int ty = t >> 3, tx = t & 7;
    const int rq = ((wy == 7) ? (ty < 4 ? 1 : 2) : 0) * 3 +
                   ((wx == 7) ? (tx < 4 ? 1 : 2) : 0);

    float s[64];
#pragma unroll
    for (int k = 0; k < 64; k++) {
        float acc = 0.f;
#pragma unroll
        for (int d4 = 0; d4 < 8; d4++) {
            const float4 kv = ((const float4*)(Ks + k * 32))[d4];
            acc += q[d4 * 4 + 0] * kv.x + q[d4 * 4 + 1] * kv.y +
                   q[d4 * 4 + 2] * kv.z + q[d4 * 4 + 3] * kv.w;
        }
        const int ky = k >> 3, kx = k & 7;
        const int rk = ((wy == 7) ? (ky < 4 ? 1 : 2) : 0) * 3 +
                       ((wx == 7) ? (kx < 4 ? 1 : 2) : 0);
        const float val = acc * SCALE_F + pe[(ty - ky + 7) * 15 + (tx - kx + 7)];
        s[k] = (rk != rq) ? -1e30f : val;
    }

    float m = -1e30f;
#pragma unroll
    for (int k = 0; k < 64; k++) m = fmaxf(m, s[k]);
    float sum = 0.f;
#pragma unroll
    for (int k = 0; k < 64; k++) { s[k] = __expf(s[k] - m); sum += s[k]; }
    const float inv = 1.f / sum;

    float o[32];
#pragma unroll
    for (int d = 0; d < 32; d++) o[d] = 0.f;
#pragma unroll
    for (int k = 0; k < 64; k++) {
        const float p = s[k];
#pragma unroll
        for (int d4 = 0; d4 < 8; d4++) {
            const float4 vv = ((const float4*)(Vs + k * 32))[d4];
            o[d4 * 4 + 0] += p * vv.x; o[d4 * 4 + 1] += p * vv.y;
            o[d4 * 4 + 2] += p * vv.z; o[d4 * 4 + 3] += p * vv.w;
        }
    }

    // bf16 hi/lo split epilogue (packed pairs)
    unsigned int hw[16], lw[16];
#pragma unroll
    for (int d4 = 0; d4 < 8; d4++) {
        float f0 = o[d4 * 4 + 0] * inv, f1 = o[d4 * 4 + 1] * inv;
        float f2 = o[d4 * 4 + 2] * inv, f3 = o[d4 * 4 + 3] * inv;
        __nv_bfloat16 h0 = __float2bfloat16_rn(f0), h1 = __float2bfloat16_rn(f1);
        __nv_bfloat16 h2 = __float2bfloat16_rn(f2), h3 = __float2bfloat16_rn(f3);
        hw[d4 * 2 + 0] = (uint32_t)__bfloat16_as_ushort(h0) | ((uint32_t)__bfloat16_as_ushort(h1) << 16);
        hw[d4 * 2 + 1] = (uint32_t)__bfloat16_as_ushort(h2) | ((uint32_t)__bfloat16_as_ushort(h3) << 16);
        lw[d4 * 2 + 0] = (uint32_t)bf_hi(f0 - __bfloat162float(h0)) | ((uint32_t)bf_hi(f1 - __bfloat162float(h1)) << 16);
        lw[d4 * 2 + 1] = (uint32_t)bf_hi(f2 - __bfloat162float(h2)) | ((uint32_t)bf_hi(f3 - __bfloat162float(h3)) << 16);
    }
    const unsigned int pb = (unsigned int)((g * 64 + t) * 128 + h * 16);
#pragma unroll
    for (int i = 0; i < 4; i++) {
        ((uint4*)(g_xhi32 + pb))[i] = make_uint4(hw[i * 4 + 0], hw[i * 4 + 1], hw[i * 4 + 2], hw[i * 4 + 3]);
        ((uint4*)(g_xlo32 + pb))[i] = make_uint4(lw[i * 4 + 0], lw[i * 4 + 1], lw[i * 4 + 2], lw[i * 4 + 3]);
    }
}

// ---------------------------------------------------------------------------
extern "C" void kernel_launch(void* const* d_in, const int* in_sizes, int n_in,
                              void* d_out, int out_size)
{
    const float* x       = (const float*)d_in[0];
    const float* w_qkv   = (const float*)d_in[1];
    const float* b_qkv   = (const float*)d_in[2];
    const float* w_out   = (const float*)d_in[3];
    const float* b_out   = (const float*)d_in[4];
    const float* pos_enc = (const float*)d_in[5];
    float* out = (float*)d_out;

    cudaFuncSetAttribute(gemm_mma_kernel<0>, cudaFuncAttributeMaxDynamicSharedMemorySize, SMEM_DYN);
    cudaFuncSetAttribute(gemm_mma_kernel<1>, cudaFuncAttributeMaxDynamicSharedMemorySize, SMEM_DYN);

    // 1) split x into bf16 hi/lo
    prep_x_kernel<<<32768, 256>>>((const float4*)x);
    // 2) split weights into bf16 hi/lo
    prep_w_kernel<<<1024, 256>>>(w_qkv, w_out);
    // 3) QKV projection (HMMA): N=768 -> 6 tiles of 128
    gemm_mma_kernel<0><<<dim3(6, 1024), 256, SMEM_DYN>>>(b_qkv, nullptr);
    // 4) windowed attention (fp32 SIMT), writes bf16 hi/lo attn output
    attn_kernel<<<NWIN * HEADS, 64>>>(pos_enc);
    // 5) output projection (HMMA) + inverse-roll scatter: N=256 -> 2 tiles
    gemm_mma_kernel<1><<<dim3(2, 1024), 256, SMEM_DYN>>>(b_out, out);
}

// round 6
// speedup vs baseline: 2.3473x; 1.3195x over previous
#include <cuda_runtime.h>
#include <cuda_bf16.h>
#include <cstdint>

// ---------------------------------------------------------------------------
// Problem constants
// ---------------------------------------------------------------------------
#define NWIN      2048
#define HEADS     8
#define WS2       64
#define HEAD_DIM  32
#define DIMC      256
#define QKV_PART  (NWIN * HEADS * WS2 * HEAD_DIM)   // 33,554,432
#define SCALE_F   0.17677669529663687f

// Scratch (static device globals — allocation-free per harness rules)
__device__ float          g_qkv[3ULL * QKV_PART];   // [part][g][h][t][d] fp32
__device__ unsigned int   g_xhi32[16777216];        // bf16 pairs of x (later: attn out), [row][k/2]
__device__ unsigned int   g_xlo32[16777216];
__device__ unsigned short g_wqhi[196608];           // w_qkv row-major bf16 hi/lo [768][256]
__device__ unsigned short g_wqlo[196608];
__device__ unsigned short g_wohi[65536];            // w_out  row-major bf16 hi/lo [256][256]
__device__ unsigned short g_wolo[65536];

// ---------------------------------------------------------------------------
// Helpers (plain-target PTX only: ldmatrix / mma.sync / cp.async)
// ---------------------------------------------------------------------------
__device__ __forceinline__ uint32_t smem_u32(const void* p) {
    uint32_t a;
    asm("{ .reg .u64 t; cvta.to.shared.u64 t, %1; cvt.u32.u64 %0, t; }" : "=r"(a) : "l"(p));
    return a;
}
__device__ __forceinline__ void cp16(uint32_t dst, const void* src) {
    asm volatile("cp.async.cg.shared.global [%0], [%1], 16;" :: "r"(dst), "l"(src));
}
#define CP_COMMIT()  asm volatile("cp.async.commit_group;")
#define CP_WAIT(n)   asm volatile("cp.async.wait_group %0;" :: "n"(n))

#define LDM4(r, addr) \
    asm volatile("ldmatrix.sync.aligned.m8n8.x4.shared.b16 {%0,%1,%2,%3}, [%4];" \
        : "=r"((r)[0]), "=r"((r)[1]), "=r"((r)[2]), "=r"((r)[3]) : "r"(addr))

#define MMA16816(c, a, b0, b1) \
    asm volatile("mma.sync.aligned.m16n8k16.row.col.f32.bf16.bf16.f32 " \
        "{%0,%1,%2,%3},{%4,%5,%6,%7},{%8,%9},{%0,%1,%2,%3};" \
        : "+f"((c)[0]), "+f"((c)[1]), "+f"((c)[2]), "+f"((c)[3]) \
        : "r"((a)[0]), "r"((a)[1]), "r"((a)[2]), "r"((a)[3]), "r"(b0), "r"(b1))

__device__ __forceinline__ unsigned short bf_hi(float f) {
    return __bfloat16_as_ushort(__float2bfloat16_rn(f));
}

// ---------------------------------------------------------------------------
// prep_x: split fp32 -> bf16 hi/lo packed-pair arrays (4 floats/thread)
// ---------------------------------------------------------------------------
__global__ __launch_bounds__(256) void prep_x_kernel(const float4* __restrict__ x4)
{
    const int gid = blockIdx.x * 256 + threadIdx.x;   // 8,388,608
    const float4 v = x4[gid];
    __nv_bfloat16 h0 = __float2bfloat16_rn(v.x), h1 = __float2bfloat16_rn(v.y);
    __nv_bfloat16 h2 = __float2bfloat16_rn(v.z), h3 = __float2bfloat16_rn(v.w);
    uint2 H, L;
    H.x = (uint32_t)__bfloat16_as_ushort(h0) | ((uint32_t)__bfloat16_as_ushort(h1) << 16);
    H.y = (uint32_t)__bfloat16_as_ushort(h2) | ((uint32_t)__bfloat16_as_ushort(h3) << 16);
    L.x = (uint32_t)bf_hi(v.x - __bfloat162float(h0)) | ((uint32_t)bf_hi(v.y - __bfloat162float(h1)) << 16);
    L.y = (uint32_t)bf_hi(v.z - __bfloat162float(h2)) | ((uint32_t)bf_hi(v.w - __bfloat162float(h3)) << 16);
    ((uint2*)g_xhi32)[gid] = H;
    ((uint2*)g_xlo32)[gid] = L;
}

// ---------------------------------------------------------------------------
// prep_w: weights -> row-major bf16 hi/lo
// ---------------------------------------------------------------------------
__global__ __launch_bounds__(256) void prep_w_kernel(const float* __restrict__ wq,
                                                     const float* __restrict__ wo)
{
    const int idx = blockIdx.x * 256 + threadIdx.x;   // 262,144
    if (idx < 196608) {
        const float v = wq[idx];
        __nv_bfloat16 h = __float2bfloat16_rn(v);
        g_wqhi[idx] = __bfloat16_as_ushort(h);
        g_wqlo[idx] = bf_hi(v - __bfloat162float(h));
    } else {
        const int i2 = idx - 196608;
        const float v = wo[i2];
        __nv_bfloat16 h = __float2bfloat16_rn(v);
        g_wohi[i2] = __bfloat16_as_ushort(h);
        g_wolo[i2] = bf_hi(v - __bfloat162float(h));
    }
}

// ---------------------------------------------------------------------------
// HMMA GEMM (unchanged from R5 — passing): block [128x128], K=256 in 8 chunks,
// cp.async double-buffered, 3-term bf16 split.
// ---------------------------------------------------------------------------
#define TILE_B    10240               // 128*80
#define BUF_B     (4 * TILE_B)        // Ahi, Alo, Bhi, Blo
#define SMEM_DYN  (2 * BUF_B)         // 81920

template <int MODE>
__global__ __launch_bounds__(256)
void gemm_mma_kernel(const float* __restrict__ bias, float* __restrict__ out)
{
    extern __shared__ char smem[];
    __shared__ int   rowoff[128];
    __shared__ float bias_s[128];

    const uint32_t sb  = smem_u32(smem);
    const int tid  = threadIdx.x;
    const int wid  = tid >> 5;
    const int lane = tid & 31;
    const int nt = blockIdx.x, mb = blockIdx.y;

    if (tid < 128) {
        const int r = tid;
        const int g = mb * 2 + (r >> 6);
        const int b = g >> 6, w = g & 63;
        const int wy = w >> 3, wx = w & 7, ty = (r >> 3) & 7, tx = r & 7;
        const int i_ = (wy * 8 + ty + 4) & 63;
        const int j_ = (wx * 8 + tx + 4) & 63;
        const int srcRow = b * 4096 + i_ * 64 + j_;
        rowoff[r] = (MODE == 0) ? srcRow * 128 : srcRow * 256;
        bias_s[r] = bias[nt * 128 + r];
    }
    __syncthreads();

    const unsigned short* wh = (MODE == 0) ? g_wqhi : g_wohi;
    const unsigned short* wl = (MODE == 0) ? g_wqlo : g_wolo;

    const int lrow = tid >> 1;
    const int q0   = (tid & 1) * 2;
    const int aRowBase = (MODE == 0) ? rowoff[lrow] : (mb * 128 + lrow) * 128;
    const int bRowBase = (nt * 128 + lrow) * 256;

    float acc[2][8][4];
#pragma unroll
    for (int i = 0; i < 2; i++)
#pragma unroll
        for (int j = 0; j < 8; j++)
#pragma unroll
            for (int k = 0; k < 4; k++) acc[i][j][k] = 0.f;

    const int a_off = ((lane & 7) + ((lane >> 3) & 1) * 8) * 80 + (lane >> 4) * 16;
    const int b_off = ((lane & 7) + ((lane >> 3) >> 1) * 8) * 80 + ((lane >> 3) & 1) * 16;
    const int wr = wid & 3;
    const int wc = wid >> 2;

#define LOAD_CHUNK(kc, buf) do { \
    const uint32_t base = sb + (buf) * BUF_B + lrow * 80; \
    _Pragma("unroll") \
    for (int j = 0; j < 2; j++) { \
        const int q = q0 + j; \
        const uint32_t d = base + q * 16; \
        cp16(d,              g_xhi32 + aRowBase + (kc) * 16 + q * 4); \
        cp16(d + TILE_B,     g_xlo32 + aRowBase + (kc) * 16 + q * 4); \
        cp16(d + 2 * TILE_B, wh + bRowBase + (kc) * 32 + q * 8); \
        cp16(d + 3 * TILE_B, wl + bRowBase + (kc) * 32 + q * 8); \
    } \
} while (0)

    LOAD_CHUNK(0, 0);
    CP_COMMIT();

    for (int kc = 0; kc < 8; kc++) {
        if (kc < 7) {
            LOAD_CHUNK(kc + 1, (kc + 1) & 1);
            CP_COMMIT();
            CP_WAIT(1);
        } else {
            CP_WAIT(0);
        }
        __syncthreads();

        const uint32_t Ab = sb + (kc & 1) * BUF_B;
        const uint32_t Bb = Ab + 2 * TILE_B;
#pragma unroll
        for (int ks = 0; ks < 2; ks++) {
            uint32_t ah[2][4], al[2][4];
#pragma unroll
            for (int mt = 0; mt < 2; mt++) {
                const uint32_t ad = Ab + (wr * 32 + mt * 16) * 80 + ks * 32 + a_off;
                LDM4(ah[mt], ad);
                LDM4(al[mt], ad + TILE_B);
            }
#pragma unroll
            for (int np = 0; np < 4; np++) {
                uint32_t bh[4], bl[4];
                const uint32_t bd = Bb + (wc * 64 + np * 16) * 80 + ks * 32 + b_off;
                LDM4(bh, bd);
                LDM4(bl, bd + TILE_B);
#pragma unroll
                for (int mt = 0; mt < 2; mt++) {
#pragma unroll
                    for (int sub = 0; sub < 2; sub++) {
                        float* c = acc[mt][np * 2 + sub];
                        MMA16816(c, ah[mt], bh[2 * sub], bh[2 * sub + 1]);
                        MMA16816(c, ah[mt], bl[2 * sub], bl[2 * sub + 1]);
                        MMA16816(c, al[mt], bh[2 * sub], bh[2 * sub + 1]);
                    }
                }
            }
        }
        __syncthreads();
    }

#pragma unroll
    for (int mt = 0; mt < 2; mt++) {
        const int R0 = wr * 32 + mt * 16 + (lane >> 2);
#pragma unroll
        for (int nti = 0; nti < 8; nti++) {
            const int cb = wc * 64 + nti * 8 + (lane & 3) * 2;
            const float bz0 = bias_s[cb], bz1 = bias_s[cb + 1];
            const float* c = acc[mt][nti];
#pragma unroll
            for (int half = 0; half < 2; half++) {
                const int R = R0 + half * 8;
                float2 v;
                v.x = c[half * 2 + 0] + bz0;
                v.y = c[half * 2 + 1] + bz1;
                if (MODE == 0) {
                    const int nn   = nt * 128 + cb;
                    const int part = nn >> 8;
                    const int h    = (nn & 255) >> 5;
                    const int d    = nn & 31;
                    const int g    = mb * 2 + (R >> 6);
                    const int t    = R & 63;
                    *(float2*)(g_qkv + (size_t)part * QKV_PART +
                               (((size_t)(g * 8 + h)) * 64 + t) * 32 + d) = v;
                } else {
                    *(float2*)(out + rowoff[R] + nt * 128 + cb) = v;
                }
            }
        }
    }
}

// ---------------------------------------------------------------------------
// Attention core v2: 8 threads per query row (4 key-slices x 2 dim-halves).
// Block = 128 threads = 16 rows of one (window, head); grid = NWIN*HEADS*4.
// Per thread: q[16], s[16], o[16] -> ~70 regs -> 6 CTAs/SM (vs 18% before).
// K/V in smem with 36-float row stride (conflict-free chunk pattern).
// ---------------------------------------------------------------------------
#define KSTRIDE 36
__global__ __launch_bounds__(128, 6)
void attn_kernel(const float* __restrict__ pos_enc)
{
    __shared__ float Ks[WS2 * KSTRIDE];
    __shared__ float Vs[WS2 * KSTRIDE];
    __shared__ float pe[225];

    const int bid = blockIdx.x;
    const int gh  = bid >> 2;
    const int q4  = bid & 3;          // row quarter
    const int g   = gh >> 3;
    const int h   = gh & 7;

    const int tid = threadIdx.x;
    const int rl  = tid >> 3;         // row within quarter: 0..15
    const int ks  = (tid >> 1) & 3;   // key slice
    const int dh  = tid & 1;          // dim half
    const int t   = q4 * 16 + rl;     // query row 0..63

    const float* Kb = g_qkv + (size_t)QKV_PART + (size_t)gh * 2048;
    const float* Vb = g_qkv + 2ULL * QKV_PART + (size_t)gh * 2048;

    // stage K/V with padded stride
    for (int i = tid; i < 512; i += 128) {
        const int k = i >> 3, d4 = i & 7;
        *(float4*)(Ks + k * KSTRIDE + d4 * 4) = ((const float4*)Kb)[i];
        *(float4*)(Vs + k * KSTRIDE + d4 * 4) = ((const float4*)Vb)[i];
    }
    for (int i = tid; i < 225; i += 128) pe[i] = pos_enc[h * 225 + i];

    // q: 16 dims for this thread's half
    float q[16];
    {
        const float* Qb = g_qkv + (size_t)gh * 2048 + (size_t)t * 32 + dh * 16;
#pragma unroll
        for (int i = 0; i < 4; i++) {
            const float4 v = ((const float4*)Qb)[i];
            q[i * 4 + 0] = v.x; q[i * 4 + 1] = v.y;
            q[i * 4 + 2] = v.z; q[i * 4 + 3] = v.w;
        }
    }
    __syncthreads();

    const int w  = g & 63;
    const int wy = w >> 3, wx = w & 7;
    const int ty = t >> 3, tx = t & 7;
    const int rq = ((wy == 7) ? (ty < 4 ? 1 : 2) : 0) * 3 +
                   ((wx == 7) ? (tx < 4 ? 1 : 2) : 0);

    // QK: this thread's 16 keys (k = 4i + ks), 16 dims (dh half)
    float s[16];
#pragma unroll
    for (int i = 0; i < 16; i++) {
        const int k = i * 4 + ks;
        const float* kp = Ks + k * KSTRIDE + dh * 16;
        float acc = 0.f;
#pragma unroll
        for (int d4 = 0; d4 < 4; d4++) {
            const float4 kv = *(const float4*)(kp + d4 * 4);
            acc += q[d4 * 4 + 0] * kv.x + q[d4 * 4 + 1] * kv.y +
                   q[d4 * 4 + 2] * kv.z + q[d4 * 4 + 3] * kv.w;
        }
        acc += __shfl_xor_sync(0xffffffffu, acc, 1);   // combine dim halves
        const int ky = k >> 3, kx = k & 7;
        const int rk = ((wy == 7) ? (ky < 4 ? 1 : 2) : 0) * 3 +
                       ((wx == 7) ? (kx < 4 ? 1 : 2) : 0);
        const float val = acc * SCALE_F + pe[(ty - ky + 7) * 15 + (tx - kx + 7)];
        s[i] = (rk != rq) ? -1e30f : val;
    }

    // softmax across the 4 key slices (lanes xor 2, xor 4)
    float m = -1e30f;
#pragma unroll
    for (int i = 0; i < 16; i++) m = fmaxf(m, s[i]);
    m = fmaxf(m, __shfl_xor_sync(0xffffffffu, m, 2));
    m = fmaxf(m, __shfl_xor_sync(0xffffffffu, m, 4));
    float sum = 0.f;
#pragma unroll
    for (int i = 0; i < 16; i++) { s[i] = __expf(s[i] - m); sum += s[i]; }
    sum += __shfl_xor_sync(0xffffffffu, sum, 2);
    sum += __shfl_xor_sync(0xffffffffu, sum, 4);
    const float inv = 1.f / sum;

    // PV: accumulate over this thread's 16 keys for its 16 dims
    float o[16];
#pragma unroll
    for (int d = 0; d < 16; d++) o[d] = 0.f;
#pragma unroll
    for (int i = 0; i < 16; i++) {
        const int k = i * 4 + ks;
        const float p = s[i];
        const float* vp = Vs + k * KSTRIDE + dh * 16;
#pragma unroll
        for (int d4 = 0; d4 < 4; d4++) {
            const float4 vv = *(const float4*)(vp + d4 * 4);
            o[d4 * 4 + 0] += p * vv.x; o[d4 * 4 + 1] += p * vv.y;
            o[d4 * 4 + 2] += p * vv.z; o[d4 * 4 + 3] += p * vv.w;
        }
    }
    // reduce over key slices
#pragma unroll
    for (int d = 0; d < 16; d++) {
        o[d] += __shfl_xor_sync(0xffffffffu, o[d], 2);
        o[d] += __shfl_xor_sync(0xffffffffu, o[d], 4);
    }

    if (ks == 0) {
        // bf16 hi/lo split epilogue for this dim half (8 packed pairs)
        unsigned int hw[8], lw[8];
#pragma unroll
        for (int p2 = 0; p2 < 8; p2++) {
            const float f0 = o[p2 * 2 + 0] * inv;
            const float f1 = o[p2 * 2 + 1] * inv;
            __nv_bfloat16 h0 = __float2bfloat16_rn(f0), h1 = __float2bfloat16_rn(f1);
            hw[p2] = (uint32_t)__bfloat16_as_ushort(h0) | ((uint32_t)__bfloat16_as_ushort(h1) << 16);
            lw[p2] = (uint32_t)bf_hi(f0 - __bfloat162float(h0)) |
                     ((uint32_t)bf_hi(f1 - __bfloat162float(h1)) << 16);
        }
        const unsigned int pb = (unsigned int)((g * 64 + t) * 128 + h * 16 + dh * 8);
        ((uint4*)(g_xhi32 + pb))[0] = make_uint4(hw[0], hw[1], hw[2], hw[3]);
        ((uint4*)(g_xhi32 + pb))[1] = make_uint4(hw[4], hw[5], hw[6], hw[7]);
        ((uint4*)(g_xlo32 + pb))[0] = make_uint4(lw[0], lw[1], lw[2], lw[3]);
        ((uint4*)(g_xlo32 + pb))[1] = make_uint4(lw[4], lw[5], lw[6], lw[7]);
    }
}

// ---------------------------------------------------------------------------
extern "C" void kernel_launch(void* const* d_in, const int* in_sizes, int n_in,
                              void* d_out, int out_size)
{
    const float* x       = (const float*)d_in[0];
    const float* w_qkv   = (const float*)d_in[1];
    const float* b_qkv   = (const float*)d_in[2];
    const float* w_out   = (const float*)d_in[3];
    const float* b_out   = (const float*)d_in[4];
    const float* pos_enc = (const float*)d_in[5];
    float* out = (float*)d_out;

    cudaFuncSetAttribute(gemm_mma_kernel<0>, cudaFuncAttributeMaxDynamicSharedMemorySize, SMEM_DYN);
    cudaFuncSetAttribute(gemm_mma_kernel<1>, cudaFuncAttributeMaxDynamicSharedMemorySize, SMEM_DYN);

    // 1) split x into bf16 hi/lo
    prep_x_kernel<<<32768, 256>>>((const float4*)x);
    // 2) split weights into bf16 hi/lo
    prep_w_kernel<<<1024, 256>>>(w_qkv, w_out);
    // 3) QKV projection (HMMA): N=768 -> 6 tiles of 128
    gemm_mma_kernel<0><<<dim3(6, 1024), 256, SMEM_DYN>>>(b_qkv, nullptr);
    // 4) windowed attention (fp32 SIMT, 8 threads/row), writes bf16 hi/lo out
    attn_kernel<<<NWIN * HEADS * 4, 128>>>(pos_enc);
    // 5) output projection (HMMA) + inverse-roll scatter: N=256 -> 2 tiles
    gemm_mma_kernel<1><<<dim3(2, 1024), 256, SMEM_DYN>>>(b_out, out);
}

// round 7
// speedup vs baseline: 3.3755x; 1.4380x over previous
#include <cuda_runtime.h>
#include <cuda_bf16.h>
#include <cstdint>

// ---------------------------------------------------------------------------
// Problem constants
// ---------------------------------------------------------------------------
#define NWIN      2048
#define HEADS     8
#define WS2       64
#define HEAD_DIM  32
#define DIMC      256
#define SCALE_F   0.17677669529663687f

// Scratch (static device globals — allocation-free per harness rules)
__device__ unsigned int   g_xhi32[16777216];   // bf16 pairs of x / attn out [row][k/2]
__device__ unsigned int   g_xlo32[16777216];
__device__ unsigned int   g_qkhi[33554432];    // Q,K bf16-hi pairs [part][g][h][t][d/2]
__device__ unsigned int   g_qklo[33554432];
__device__ unsigned short g_vthi16[33554432];  // V^T bf16 [g][h][d][t]
__device__ unsigned short g_vtlo16[33554432];
__device__ unsigned short g_wqhi[196608];      // w_qkv row-major bf16 hi/lo [768][256]
__device__ unsigned short g_wqlo[196608];
__device__ unsigned short g_wohi[65536];       // w_out  row-major bf16 hi/lo [256][256]
__device__ unsigned short g_wolo[65536];

// ---------------------------------------------------------------------------
// Helpers (plain-target PTX only: ldmatrix / mma.sync / cp.async)
// ---------------------------------------------------------------------------
__device__ __forceinline__ uint32_t smem_u32(const void* p) {
    uint32_t a;
    asm("{ .reg .u64 t; cvta.to.shared.u64 t, %1; cvt.u32.u64 %0, t; }" : "=r"(a) : "l"(p));
    return a;
}
__device__ __forceinline__ void cp16(uint32_t dst, const void* src) {
    asm volatile("cp.async.cg.shared.global [%0], [%1], 16;" :: "r"(dst), "l"(src));
}
#define CP_COMMIT()  asm volatile("cp.async.commit_group;")
#define CP_WAIT(n)   asm volatile("cp.async.wait_group %0;" :: "n"(n))

#define LDM4(r, addr) \
    asm volatile("ldmatrix.sync.aligned.m8n8.x4.shared.b16 {%0,%1,%2,%3}, [%4];" \
        : "=r"((r)[0]), "=r"((r)[1]), "=r"((r)[2]), "=r"((r)[3]) : "r"(addr))

#define MMA16816(c, a, b0, b1) \
    asm volatile("mma.sync.aligned.m16n8k16.row.col.f32.bf16.bf16.f32 " \
        "{%0,%1,%2,%3},{%4,%5,%6,%7},{%8,%9},{%0,%1,%2,%3};" \
        : "+f"((c)[0]), "+f"((c)[1]), "+f"((c)[2]), "+f"((c)[3]) \
        : "r"((a)[0]), "r"((a)[1]), "r"((a)[2]), "r"((a)[3]), "r"(b0), "r"(b1))

__device__ __forceinline__ unsigned short bf_hi(float f) {
    return __bfloat16_as_ushort(__float2bfloat16_rn(f));
}
__device__ __forceinline__ uint32_t pack2(float a, float b) {
    return (uint32_t)bf_hi(a) | ((uint32_t)bf_hi(b) << 16);
}

// ---------------------------------------------------------------------------
// prep_x: split fp32 -> bf16 hi/lo packed-pair arrays (4 floats/thread)
// ---------------------------------------------------------------------------
__global__ __launch_bounds__(256) void prep_x_kernel(const float4* __restrict__ x4)
{
    const int gid = blockIdx.x * 256 + threadIdx.x;   // 8,388,608
    const float4 v = x4[gid];
    __nv_bfloat16 h0 = __float2bfloat16_rn(v.x), h1 = __float2bfloat16_rn(v.y);
    __nv_bfloat16 h2 = __float2bfloat16_rn(v.z), h3 = __float2bfloat16_rn(v.w);
    uint2 H, L;
    H.x = (uint32_t)__bfloat16_as_ushort(h0) | ((uint32_t)__bfloat16_as_ushort(h1) << 16);
    H.y = (uint32_t)__bfloat16_as_ushort(h2) | ((uint32_t)__bfloat16_as_ushort(h3) << 16);
    L.x = (uint32_t)bf_hi(v.x - __bfloat162float(h0)) | ((uint32_t)bf_hi(v.y - __bfloat162float(h1)) << 16);
    L.y = (uint32_t)bf_hi(v.z - __bfloat162float(h2)) | ((uint32_t)bf_hi(v.w - __bfloat162float(h3)) << 16);
    ((uint2*)g_xhi32)[gid] = H;
    ((uint2*)g_xlo32)[gid] = L;
}

// ---------------------------------------------------------------------------
// prep_w: weights -> row-major bf16 hi/lo
// ---------------------------------------------------------------------------
__global__ __launch_bounds__(256) void prep_w_kernel(const float* __restrict__ wq,
                                                     const float* __restrict__ wo)
{
    const int idx = blockIdx.x * 256 + threadIdx.x;   // 262,144
    if (idx < 196608) {
        const float v = wq[idx];
        __nv_bfloat16 h = __float2bfloat16_rn(v);
        g_wqhi[idx] = __bfloat16_as_ushort(h);
        g_wqlo[idx] = bf_hi(v - __bfloat162float(h));
    } else {
        const int i2 = idx - 196608;
        const float v = wo[i2];
        __nv_bfloat16 h = __float2bfloat16_rn(v);
        g_wohi[i2] = __bfloat16_as_ushort(h);
        g_wolo[i2] = bf_hi(v - __bfloat162float(h));
    }
}

// ---------------------------------------------------------------------------
// HMMA GEMM: block [128x128], K=256 in 8 chunks, cp.async double-buffered,
// 3-term bf16 split.
// MODE 0: A = x (roll gather), C -> bf16 hi/lo qkv (Q,K pair layout; V transposed)
// MODE 1: A = attn out,        C -> d_out fp32 (inverse-roll scatter)
// ---------------------------------------------------------------------------
#define TILE_B    10240               // 128*80
#define BUF_B     (4 * TILE_B)        // Ahi, Alo, Bhi, Blo
#define SMEM_DYN  (2 * BUF_B)         // 81920

template <int MODE>
__global__ __launch_bounds__(256)
void gemm_mma_kernel(const float* __restrict__ bias, float* __restrict__ out)
{
    extern __shared__ char smem[];
    __shared__ int   rowoff[128];
    __shared__ float bias_s[128];

    const uint32_t sb  = smem_u32(smem);
    const int tid  = threadIdx.x;
    const int wid  = tid >> 5;
    const int lane = tid & 31;
    const int nt = blockIdx.x, mb = blockIdx.y;

    if (tid < 128) {
        const int r = tid;
        const int g = mb * 2 + (r >> 6);
        const int b = g >> 6, w = g & 63;
        const int wy = w >> 3, wx = w & 7, ty = (r >> 3) & 7, tx = r & 7;
        const int i_ = (wy * 8 + ty + 4) & 63;
        const int j_ = (wx * 8 + tx + 4) & 63;
        const int srcRow = b * 4096 + i_ * 64 + j_;
        rowoff[r] = (MODE == 0) ? srcRow * 128 : srcRow * 256;
        bias_s[r] = bias[nt * 128 + r];
    }
    __syncthreads();

    const unsigned short* wh = (MODE == 0) ? g_wqhi : g_wohi;
    const unsigned short* wl = (MODE == 0) ? g_wqlo : g_wolo;

    const int lrow = tid >> 1;
    const int q0   = (tid & 1) * 2;
    const int aRowBase = (MODE == 0) ? rowoff[lrow] : (mb * 128 + lrow) * 128;
    const int bRowBase = (nt * 128 + lrow) * 256;

    float acc[2][8][4];
#pragma unroll
    for (int i = 0; i < 2; i++)
#pragma unroll
        for (int j = 0; j < 8; j++)
#pragma unroll
            for (int k = 0; k < 4; k++) acc[i][j][k] = 0.f;

    const int a_off = ((lane & 7) + ((lane >> 3) & 1) * 8) * 80 + (lane >> 4) * 16;
    const int b_off = ((lane & 7) + ((lane >> 3) >> 1) * 8) * 80 + ((lane >> 3) & 1) * 16;
    const int wr = wid & 3;
    const int wc = wid >> 2;

#define LOAD_CHUNK(kc, buf) do { \
    const uint32_t base = sb + (buf) * BUF_B + lrow * 80; \
    _Pragma("unroll") \
    for (int j = 0; j < 2; j++) { \
        const int q = q0 + j; \
        const uint32_t d = base + q * 16; \
        cp16(d,              g_xhi32 + aRowBase + (kc) * 16 + q * 4); \
        cp16(d + TILE_B,     g_xlo32 + aRowBase + (kc) * 16 + q * 4); \
        cp16(d + 2 * TILE_B, wh + bRowBase + (kc) * 32 + q * 8); \
        cp16(d + 3 * TILE_B, wl + bRowBase + (kc) * 32 + q * 8); \
    } \
} while (0)

    LOAD_CHUNK(0, 0);
    CP_COMMIT();

    for (int kc = 0; kc < 8; kc++) {
        if (kc < 7) {
            LOAD_CHUNK(kc + 1, (kc + 1) & 1);
            CP_COMMIT();
            CP_WAIT(1);
        } else {
            CP_WAIT(0);
        }
        __syncthreads();

        const uint32_t Ab = sb + (kc & 1) * BUF_B;
        const uint32_t Bb = Ab + 2 * TILE_B;
#pragma unroll
        for (int ks = 0; ks < 2; ks++) {
            uint32_t ah[2][4], al[2][4];
#pragma unroll
            for (int mt = 0; mt < 2; mt++) {
                const uint32_t ad = Ab + (wr * 32 + mt * 16) * 80 + ks * 32 + a_off;
                LDM4(ah[mt], ad);
                LDM4(al[mt], ad + TILE_B);
            }
#pragma unroll
            for (int np = 0; np < 4; np++) {
                uint32_t bh[4], bl[4];
                const uint32_t bd = Bb + (wc * 64 + np * 16) * 80 + ks * 32 + b_off;
                LDM4(bh, bd);
                LDM4(bl, bd + TILE_B);
#pragma unroll
                for (int mt = 0; mt < 2; mt++) {
#pragma unroll
                    for (int sub = 0; sub < 2; sub++) {
                        float* c = acc[mt][np * 2 + sub];
                        MMA16816(c, ah[mt], bh[2 * sub], bh[2 * sub + 1]);
                        MMA16816(c, ah[mt], bl[2 * sub], bl[2 * sub + 1]);
                        MMA16816(c, al[mt], bh[2 * sub], bh[2 * sub + 1]);
                    }
                }
            }
        }
        __syncthreads();
    }

#pragma unroll
    for (int mt = 0; mt < 2; mt++) {
        const int R0 = wr * 32 + mt * 16 + (lane >> 2);
#pragma unroll
        for (int nti = 0; nti < 8; nti++) {
            const int cb = wc * 64 + nti * 8 + (lane & 3) * 2;
            const float bz0 = bias_s[cb], bz1 = bias_s[cb + 1];
            const float* c = acc[mt][nti];
#pragma unroll
            for (int half = 0; half < 2; half++) {
                const int R = R0 + half * 8;
                float2 v;
                v.x = c[half * 2 + 0] + bz0;
                v.y = c[half * 2 + 1] + bz1;
                if (MODE == 0) {
                    const int nn   = nt * 128 + cb;
                    const int part = nn >> 8;
                    const int h    = (nn & 255) >> 5;
                    const int d    = nn & 31;
                    const int g    = mb * 2 + (R >> 6);
                    const int t    = R & 63;
                    __nv_bfloat16 h0 = __float2bfloat16_rn(v.x);
                    __nv_bfloat16 h1 = __float2bfloat16_rn(v.y);
                    const unsigned short l0 = bf_hi(v.x - __bfloat162float(h0));
                    const unsigned short l1 = bf_hi(v.y - __bfloat162float(h1));
                    if (part < 2) {
                        const size_t idx = (size_t)part * 16777216 +
                            (((size_t)(g * 8 + h)) * 64 + t) * 16 + (d >> 1);
                        g_qkhi[idx] = (uint32_t)__bfloat16_as_ushort(h0) |
                                      ((uint32_t)__bfloat16_as_ushort(h1) << 16);
                        g_qklo[idx] = (uint32_t)l0 | ((uint32_t)l1 << 16);
                    } else {
                        const size_t bidx = (((size_t)(g * 8 + h)) * 32 + d) * 64 + t;
                        g_vthi16[bidx]      = __bfloat16_as_ushort(h0);
                        g_vthi16[bidx + 64] = __bfloat16_as_ushort(h1);
                        g_vtlo16[bidx]      = l0;
                        g_vtlo16[bidx + 64] = l1;
                    }
                } else {
                    *(float2*)(out + rowoff[R] + nt * 128 + cb) = v;
                }
            }
        }
    }
}

// ---------------------------------------------------------------------------
// Attention core v3 (HMMA): block = 256 thr = 2 heads x 4 warps.
// Warp computes 16 q-rows: S = Q K^T (3-term bf16), analytic bias+mask,
// softmax via shfl (row in a lane quad), P repacked in-register to A-frags,
// O = P V via transposed-V fragments (3-term). grid = NWIN * 4 head-pairs.
// smem per head: Qhi/Qlo/Khi/Klo 64x80B, Vthi/Vtlo 32x144B. (+pe)
// ---------------------------------------------------------------------------
#define AT_HEAD_B   29696     // 4*5120 + 2*4608
#define AT_PE_OFF   59392
#define AT_SMEM     61440

__global__ __launch_bounds__(256, 2)
void attn_kernel(const float* __restrict__ pos_enc)
{
    extern __shared__ char smem[];
    const uint32_t sb = smem_u32(smem);
    const int tid  = threadIdx.x;
    const int wid  = tid >> 5;
    const int lane = tid & 31;

    const int g  = blockIdx.x >> 2;     // window
    const int hp = blockIdx.x & 3;      // head pair

    // ---- stage Q,K (hi/lo) ----
#pragma unroll
    for (int it = 0; it < 8; it++) {
        const int i = tid + it * 256;           // 0..2047
        const int hd  = i >> 10;
        const int tsr = (i >> 8) & 3;           // 0:Qh 1:Ql 2:Kh 3:Kl
        const int row = (i >> 2) & 63;
        const int q16 = i & 3;
        const int part = tsr >> 1, prec = tsr & 1;
        const unsigned int* src = (prec ? g_qklo : g_qkhi) + (size_t)part * 16777216 +
            (((size_t)(g * 8 + hp * 2 + hd)) * 64 + row) * 16 + q16 * 4;
        cp16(sb + hd * AT_HEAD_B + tsr * 5120 + row * 80 + q16 * 16, src);
    }
    // ---- stage V^T (hi/lo) ----
#pragma unroll
    for (int it = 0; it < 4; it++) {
        const int i = tid + it * 256;           // 0..1023
        const int hd   = i >> 9;
        const int prec = (i >> 8) & 1;
        const int row  = (i >> 3) & 31;         // dim
        const int q    = i & 7;
        const unsigned short* src = (prec ? g_vtlo16 : g_vthi16) +
            (((size_t)(g * 8 + hp * 2 + hd)) * 32 + row) * 64 + q * 8;
        cp16(sb + hd * AT_HEAD_B + 20480 + prec * 4608 + row * 144 + q * 16, src);
    }
    CP_COMMIT();
    // ---- pe slices ----
    float* pe_s = (float*)(smem + AT_PE_OFF);
    for (int i = tid; i < 450; i += 256) {
        const int hd = i / 225, j = i - hd * 225;
        pe_s[hd * 240 + j] = pos_enc[(hp * 2 + hd) * 225 + j];
    }
    CP_WAIT(0);
    __syncthreads();

    const int hd = wid >> 2;        // head within pair
    const int wq = wid & 3;         // row-block (16 rows)
    const int h  = hp * 2 + hd;
    const uint32_t hb = sb + hd * AT_HEAD_B;
    const float* pe = pe_s + hd * 240;

    const int a_off  = ((lane & 7) + ((lane >> 3) & 1) * 8) * 80 + (lane >> 4) * 16;
    const int b_off  = ((lane & 7) + ((lane >> 3) >> 1) * 8) * 80 + ((lane >> 3) & 1) * 16;
    const int vb_off = ((lane & 7) + ((lane >> 3) >> 1) * 8) * 144 + ((lane >> 3) & 1) * 16;

    // ---- S = Q K^T (3-term) ----
    float sacc[8][4];
#pragma unroll
    for (int j = 0; j < 8; j++)
#pragma unroll
        for (int e = 0; e < 4; e++) sacc[j][e] = 0.f;

#pragma unroll
    for (int ks = 0; ks < 2; ks++) {
        uint32_t ah[4], al[4];
        const uint32_t ad = hb + (wq * 16) * 80 + ks * 32 + a_off;
        LDM4(ah, ad);                 // Qhi
        LDM4(al, ad + 5120);          // Qlo
#pragma unroll
        for (int ntk = 0; ntk < 4; ntk++) {
            uint32_t bh[4], bl[4];
            const uint32_t bd = hb + 10240 + (ntk * 16) * 80 + ks * 32 + b_off;
            LDM4(bh, bd);             // Khi
            LDM4(bl, bd + 5120);      // Klo
#pragma unroll
            for (int sub = 0; sub < 2; sub++) {
                float* c = sacc[ntk * 2 + sub];
                MMA16816(c, ah, bh[2 * sub], bh[2 * sub + 1]);
                MMA16816(c, ah, bl[2 * sub], bl[2 * sub + 1]);
                MMA16816(c, al, bh[2 * sub], bh[2 * sub + 1]);
            }
        }
    }

    // ---- bias + mask ----
    const int w  = g & 63;
    const int wy = w >> 3, wx = w & 7;
    const bool eY = (wy == 7), eX = (wx == 7);
    const int R  = wq * 16 + (lane >> 2);        // row (and R+8)
    const int ty0 = R >> 3,       tx0 = R & 7;
    const int ty1 = (R + 8) >> 3, tx1 = (R + 8) & 7;
    const int rq0 = (eY ? ((ty0 < 4) ? 1 : 2) : 0) * 3 + (eX ? ((tx0 < 4) ? 1 : 2) : 0);
    const int rq1 = (eY ? ((ty1 < 4) ? 1 : 2) : 0) * 3 + (eX ? ((tx1 < 4) ? 1 : 2) : 0);

#pragma unroll
    for (int j = 0; j < 8; j++) {
#pragma unroll
        for (int e = 0; e < 2; e++) {
            const int n  = j * 8 + (lane & 3) * 2 + e;
            const int ky = n >> 3, kx = n & 7;
            const int rk = (eY ? ((ky < 4) ? 1 : 2) : 0) * 3 + (eX ? ((kx < 4) ? 1 : 2) : 0);
            sacc[j][e]     = (rk != rq0) ? -1e30f
                : (sacc[j][e]     * SCALE_F + pe[(ty0 - ky + 7) * 15 + (tx0 - kx + 7)]);
            sacc[j][e + 2] = (rk != rq1) ? -1e30f
                : (sacc[j][e + 2] * SCALE_F + pe[(ty1 - ky + 7) * 15 + (tx1 - kx + 7)]);
        }
    }

    // ---- softmax (rows R, R+8; each row lives in a lane quad) ----
    float m0 = -1e30f, m1 = -1e30f;
#pragma unroll
    for (int j = 0; j < 8; j++) {
        m0 = fmaxf(m0, fmaxf(sacc[j][0], sacc[j][1]));
        m1 = fmaxf(m1, fmaxf(sacc[j][2], sacc[j][3]));
    }
    m0 = fmaxf(m0, __shfl_xor_sync(0xffffffffu, m0, 1));
    m0 = fmaxf(m0, __shfl_xor_sync(0xffffffffu, m0, 2));
    m1 = fmaxf(m1, __shfl_xor_sync(0xffffffffu, m1, 1));
    m1 = fmaxf(m1, __shfl_xor_sync(0xffffffffu, m1, 2));
    float s0 = 0.f, s1 = 0.f;
#pragma unroll
    for (int j = 0; j < 8; j++) {
        sacc[j][0] = __expf(sacc[j][0] - m0); s0 += sacc[j][0];
        sacc[j][1] = __expf(sacc[j][1] - m0); s0 += sacc[j][1];
        sacc[j][2] = __expf(sacc[j][2] - m1); s1 += sacc[j][2];
        sacc[j][3] = __expf(sacc[j][3] - m1); s1 += sacc[j][3];
    }
    s0 += __shfl_xor_sync(0xffffffffu, s0, 1);
    s0 += __shfl_xor_sync(0xffffffffu, s0, 2);
    s1 += __shfl_xor_sync(0xffffffffu, s1, 1);
    s1 += __shfl_xor_sync(0xffffffffu, s1, 2);
    const float inv0 = 1.f / s0, inv1 = 1.f / s1;

    // ---- P -> bf16 hi/lo A-frags (in-register repack) ----
    uint32_t pa[4][4], pl[4][4];
#pragma unroll
    for (int s = 0; s < 4; s++) {
        const int j0 = 2 * s, j1 = 2 * s + 1;
        const float p00 = sacc[j0][0] * inv0, p01 = sacc[j0][1] * inv0;
        const float p02 = sacc[j0][2] * inv1, p03 = sacc[j0][3] * inv1;
        const float p10 = sacc[j1][0] * inv0, p11 = sacc[j1][1] * inv0;
        const float p12 = sacc[j1][2] * inv1, p13 = sacc[j1][3] * inv1;
        pa[s][0] = pack2(p00, p01);  pa[s][1] = pack2(p02, p03);
        pa[s][2] = pack2(p10, p11);  pa[s][3] = pack2(p12, p13);
        pl[s][0] = pack2(p00 - __bfloat162float(__float2bfloat16_rn(p00)),
                         p01 - __bfloat162float(__float2bfloat16_rn(p01)));
        pl[s][1] = pack2(p02 - __bfloat162float(__float2bfloat16_rn(p02)),
                         p03 - __bfloat162float(__float2bfloat16_rn(p03)));
        pl[s][2] = pack2(p10 - __bfloat162float(__float2bfloat16_rn(p10)),
                         p11 - __bfloat162float(__float2bfloat16_rn(p11)));
        pl[s][3] = pack2(p12 - __bfloat162float(__float2bfloat16_rn(p12)),
                         p13 - __bfloat162float(__float2bfloat16_rn(p13)));
    }

    // ---- O = P V (3-term, V^T fragments) ----
    float oacc[4][4];
#pragma unroll
    for (int j = 0; j < 4; j++)
#pragma unroll
        for (int e = 0; e < 4; e++) oacc[j][e] = 0.f;

#pragma unroll
    for (int ks = 0; ks < 4; ks++) {              // key steps of 16
        uint32_t vh[2][4], vl[2][4];
#pragma unroll
        for (int nt16 = 0; nt16 < 2; nt16++) {    // dim tiles of 16
            const uint32_t vd = hb + 20480 + (nt16 * 16) * 144 + ks * 32 + vb_off;
            LDM4(vh[nt16], vd);
            LDM4(vl[nt16], vd + 4608);
        }
#pragma unroll
        for (int nt8 = 0; nt8 < 4; nt8++) {
            float* c = oacc[nt8];
            const uint32_t b0h = vh[nt8 >> 1][2 * (nt8 & 1)], b1h = vh[nt8 >> 1][2 * (nt8 & 1) + 1];
            const uint32_t b0l = vl[nt8 >> 1][2 * (nt8 & 1)], b1l = vl[nt8 >> 1][2 * (nt8 & 1) + 1];
            MMA16816(c, pa[ks], b0h, b1h);
            MMA16816(c, pl[ks], b0h, b1h);
            MMA16816(c, pa[ks], b0l, b1l);
        }
    }

    // ---- epilogue: bf16 hi/lo split of O into g_x buffers ----
#pragma unroll
    for (int nt8 = 0; nt8 < 4; nt8++) {
        const int n = nt8 * 8 + (lane & 3) * 2;
#pragma unroll
        for (int half = 0; half < 2; half++) {
            const int row = R + half * 8;
            const float f0 = oacc[nt8][half * 2 + 0];
            const float f1 = oacc[nt8][half * 2 + 1];
            __nv_bfloat16 h0 = __float2bfloat16_rn(f0), h1 = __float2bfloat16_rn(f1);
            const size_t idx = ((size_t)(g * 64 + row)) * 128 + h * 16 + (n >> 1);
            g_xhi32[idx] = (uint32_t)__bfloat16_as_ushort(h0) |
                           ((uint32_t)__bfloat16_as_ushort(h1) << 16);
            g_xlo32[idx] = (uint32_t)bf_hi(f0 - __bfloat162float(h0)) |
                           ((uint32_t)bf_hi(f1 - __bfloat162float(h1)) << 16);
        }
    }
}

// ---------------------------------------------------------------------------
extern "C" void kernel_launch(void* const* d_in, const int* in_sizes, int n_in,
                              void* d_out, int out_size)
{
    const float* x       = (const float*)d_in[0];
    const float* w_qkv   = (const float*)d_in[1];
    const float* b_qkv   = (const float*)d_in[2];
    const float* w_out   = (const float*)d_in[3];
    const float* b_out   = (const float*)d_in[4];
    const float* pos_enc = (const float*)d_in[5];
    float* out = (float*)d_out;

    cudaFuncSetAttribute(gemm_mma_kernel<0>, cudaFuncAttributeMaxDynamicSharedMemorySize, SMEM_DYN);
    cudaFuncSetAttribute(gemm_mma_kernel<1>, cudaFuncAttributeMaxDynamicSharedMemorySize, SMEM_DYN);
    cudaFuncSetAttribute(attn_kernel, cudaFuncAttributeMaxDynamicSharedMemorySize, AT_SMEM);

    // 1) split x into bf16 hi/lo
    prep_x_kernel<<<32768, 256>>>((const float4*)x);
    // 2) split weights into bf16 hi/lo
    prep_w_kernel<<<1024, 256>>>(w_qkv, w_out);
    // 3) QKV projection (HMMA) -> bf16 hi/lo Q,K pairs + transposed V
    gemm_mma_kernel<0><<<dim3(6, 1024), 256, SMEM_DYN>>>(b_qkv, nullptr);
    // 4) windowed attention (HMMA core)
    attn_kernel<<<NWIN * 4, 256, AT_SMEM>>>(pos_enc);
    // 5) output projection (HMMA) + inverse-roll scatter
    gemm_mma_kernel<1><<<dim3(2, 1024), 256, SMEM_DYN>>>(b_out, out);
}